// round 10
// baseline (speedup 1.0000x reference)
#include <cuda_runtime.h>

// Shapes fixed by setup_inputs
#define B_ 64
#define T_ 4096
#define F_ 64
#define H_ 256
#define EPSV 1e-8f

// Chunked scan: lambda=0.5 -> 32-step warm-up error ~0.5^32.
#define CHUNK 64
#define NCHUNK (T_ / CHUNK)        // 64
#define WARM 32

#define NS (B_ * NCHUNK)           // 4096 scan blocks
#define NM 16                      // mse blocks
#define NB (NS + NM)

__device__ float g_part[NB];
__device__ unsigned int g_cnt = 0;

// One fg "pass" = 4 rows per warp, 8 lanes/row, 8 independent LDG.128 per lane.
#define FG_LOAD(p) {                                                          \
    const float4* rp = fgb + (size_t)(wbase + 4 * (p) + sub) * (H_ / 4) + col0; \
    a0 = rp[0];  a1 = rp[8];  a2 = rp[16]; a3 = rp[24];                       \
    a4 = rp[32]; a5 = rp[40]; a6 = rp[48]; a7 = rp[56]; }

#define FG_RED(p) {                                                           \
    float s =                                                                 \
      (((a0.x + a0.y) + (a0.z + a0.w)) + ((a1.x + a1.y) + (a1.z + a1.w))) +   \
      (((a2.x + a2.y) + (a2.z + a2.w)) + ((a3.x + a3.y) + (a3.z + a3.w))) +   \
      (((a4.x + a4.y) + (a4.z + a4.w)) + ((a5.x + a5.y) + (a5.z + a5.w))) +   \
      (((a6.x + a6.y) + (a6.z + a6.w)) + ((a7.x + a7.y) + (a7.z + a7.w)));    \
    s += __shfl_xor_sync(0xffffffffu, s, 1);                                  \
    s += __shfl_xor_sync(0xffffffffu, s, 2);                                  \
    s += __shfl_xor_sync(0xffffffffu, s, 4);                                  \
    if (col0 == 0) fgsum_s[wbase + 4 * (p) + sub] = s; }

#define SCAN_WARM(tt) {                                                       \
    float xt = __ldg(base + (size_t)(tt) * F_);                               \
    m = 0.5f * (m + xt);                                                      \
    float d = xt - m;                                                         \
    v = 0.5f * (v + d * d);                                                   \
    c = 0.5f * (c + d * (xl - m));                                            \
    xl = xt; }

#define SCAN_MAIN(jj) {                                                       \
    float xt = __ldg(base + (size_t)(t0 + (jj)) * F_);                        \
    m = 0.5f * (m + xt);                                                      \
    float d = xt - m;                                                         \
    v = 0.5f * (v + d * d);                                                   \
    c = 0.5f * (c + d * (xl - m));                                            \
    xl = xt;                                                                  \
    float ac = c * rsqrtf(v * v + EPSV);                                      \
    acc += (1.0f - fabsf(ac)) * fgsum_s[(jj)]; }

// ---------------------------------------------------------------------------
// Fused kernel, software-pipelined: fg loads for pass p+1 stay outstanding in
// registers while scan steps execute, so DRAM is fed during the scan chain.
// ---------------------------------------------------------------------------
__global__ void __launch_bounds__(64) k_main(const float* __restrict__ seq,
                                             const float4* __restrict__ fg,
                                             const float4* __restrict__ inp,
                                             const float4* __restrict__ tgt,
                                             float* __restrict__ out) {
    __shared__ float fgsum_s[CHUNK];
    __shared__ float sh[2];
    __shared__ int is_last;

    int tid = threadIdx.x;
    int warp = tid >> 5, lane = tid & 31;

    if (blockIdx.x < NS) {
        int b = blockIdx.x / NCHUNK;
        int chunk = blockIdx.x % NCHUNK;
        int t0 = chunk * CHUNK;

        // fg pass geometry: warp covers warp-local rows [warp*32, warp*32+32)
        const float4* fgb = fg + (size_t)(b * T_ + t0) * (H_ / 4);
        int wbase = warp * 32;
        int sub = lane >> 3;       // 0..3: row within pass
        int col0 = lane & 7;       // float4 column start
        float4 a0, a1, a2, a3, a4, a5, a6, a7;

        const float* base = seq + (size_t)b * T_ * F_ + tid;
        float m = 0.f, v = EPSV, c = 0.f, acc = 0.f, xl;

        if (chunk != 0) {
            int ts = t0 - WARM;
            xl = __ldg(base + (size_t)(ts - 1) * F_);

            // 32 warm steps interleaved with passes 0..3 (pass 4 issued)
            FG_LOAD(0)
#pragma unroll
            for (int p = 0; p < 4; ++p) {
#pragma unroll
                for (int q = 0; q < 8; ++q) SCAN_WARM(ts + p * 8 + q)
                FG_RED(p)
                FG_LOAD(p + 1)
            }
            __syncthreads();          // rows 0..16 / 32..48 visible

            // main j=0..15 interleaved with passes 4..7
#pragma unroll
            for (int p = 4; p < 8; ++p) {
#pragma unroll
                for (int q = 0; q < 4; ++q) SCAN_MAIN((p - 4) * 4 + q)
                FG_RED(p)
                if (p < 7) FG_LOAD(p + 1)
            }
            __syncthreads();          // all 64 fgsum visible

            // remaining main j=16..63
#pragma unroll 8
            for (int j = 16; j < CHUNK; ++j) SCAN_MAIN(j)
        } else {
            // chunk 0: produce all fg first (no warm-up available to overlap)
            FG_LOAD(0)
#pragma unroll
            for (int p = 0; p < 8; ++p) {
                FG_RED(p)
                if (p < 7) FG_LOAD(p + 1)
            }
            __syncthreads();
            xl = __ldg(base);
            acc = fgsum_s[0];          // t=0 pad: irr==1
#pragma unroll 8
            for (int j = 1; j < CHUNK; ++j) SCAN_MAIN(j)
        }

#pragma unroll
        for (int o = 16; o > 0; o >>= 1) acc += __shfl_xor_sync(0xffffffffu, acc, o);
        if (lane == 0) sh[warp] = acc;
        __syncthreads();
        if (tid == 0) {
            // ALPHA / (B*T*H*F) = 0.5 / 2^32
            g_part[blockIdx.x] = (sh[0] + sh[1]) * (0.5f / 4294967296.0f);
        }
    } else {
        // ---- MSE role ----
        int bid = blockIdx.x - NS;
        const int n4 = (B_ * T_) / 4;
        float acc = 0.f;
        for (int i = bid * 64 + tid; i < n4; i += NM * 64) {
            float4 a = inp[i], b = tgt[i];
            float dx = a.x - b.x, dy = a.y - b.y, dz = a.z - b.z, dw = a.w - b.w;
            acc += dx * dx + dy * dy + dz * dz + dw * dw;
        }
#pragma unroll
        for (int o = 16; o > 0; o >>= 1) acc += __shfl_xor_sync(0xffffffffu, acc, o);
        if (lane == 0) sh[warp] = acc;
        __syncthreads();
        if (tid == 0)
            g_part[blockIdx.x] = (sh[0] + sh[1]) * (1.0f / ((float)B_ * T_));
    }

    // ---- last-block finalize (threadfence reduction, graph-replay safe) ----
    if (tid == 0) {
        __threadfence();
        unsigned int t = atomicAdd(&g_cnt, 1u);
        is_last = (t == NB - 1);
    }
    __syncthreads();
    if (is_last) {
        double s = 0.0;
        for (int i = tid; i < NB; i += 64) s += (double)g_part[i];
#pragma unroll
        for (int o = 16; o > 0; o >>= 1) s += __shfl_xor_sync(0xffffffffu, s, o);
        __shared__ double sd[2];
        if (lane == 0) sd[warp] = s;
        __syncthreads();
        if (tid == 0) {
            out[0] = (float)(sd[0] + sd[1]);
            g_cnt = 0;                       // reset for next graph replay
        }
    }
}

// ---------------------------------------------------------------------------
extern "C" void kernel_launch(void* const* d_in, const int* in_sizes, int n_in,
                              void* d_out, int out_size) {
    const float* input  = (const float*)d_in[0];
    const float* target = (const float*)d_in[1];
    const float* seq    = (const float*)d_in[2];
    const float* fg     = (const float*)d_in[3];

    k_main<<<NB, 64>>>(seq, (const float4*)fg,
                       (const float4*)input, (const float4*)target,
                       (float*)d_out);
}

// round 11
// speedup vs baseline: 1.0505x; 1.0505x over previous
#include <cuda_runtime.h>

// Shapes fixed by setup_inputs
#define B_ 64
#define T_ 4096
#define F_ 64
#define H_ 256
#define EPSV 1e-8f

// Chunked scan: lambda=0.5 -> 32-step warm-up error ~0.5^32.
#define CHUNK 64
#define NCHUNK (T_ / CHUNK)        // 64
#define WARM 32

#define NS (B_ * NCHUNK)           // 4096 scan blocks
#define NM 16                      // mse blocks
#define NB (NS + NM)

__device__ float g_part[NB];
__device__ unsigned int g_cnt = 0;

// ---------------------------------------------------------------------------
// Warp-specialized fused kernel. Block (128 thr) handles one (b, chunk):
//   warps 0-1: EW autocorr scan, f = tid in [0,64). Warm-up runs BEFORE the
//              sync, concurrent with fg warps' loads. Main loop reads fgsum_s.
//   warps 2-3: reduce the chunk's 64x256 forget_gates slice into fgsum_s.
//              Octet layout: 8 lanes/row, 8 independent LDG.128/lane, 3 shfls.
// The SM therefore always holds a mix of BW-bound and latency-bound warps.
//  [NS, NB): MSE partial blocks. Last arriving block finalizes (threadfence).
// ---------------------------------------------------------------------------
__global__ void __launch_bounds__(128) k_main(const float* __restrict__ seq,
                                              const float4* __restrict__ fg,
                                              const float4* __restrict__ inp,
                                              const float4* __restrict__ tgt,
                                              float* __restrict__ out) {
    __shared__ float fgsum_s[CHUNK];
    __shared__ float sh[4];
    __shared__ int is_last;

    int tid = threadIdx.x;
    int warp = tid >> 5, lane = tid & 31;

    if (blockIdx.x < NS) {
        int b = blockIdx.x / NCHUNK;
        int chunk = blockIdx.x % NCHUNK;
        int t0 = chunk * CHUNK;

        float m = 0.f, v = EPSV, c = 0.f, acc = 0.f, xl = 0.f;

        if (warp >= 2) {
            // ================= fg role (warps 2,3) =================
            const float4* fgb = fg + (size_t)(b * T_ + t0) * (H_ / 4);
            int fw = warp - 2;               // 0 or 1 -> rows fw*32..fw*32+31
            int sub = lane >> 3;             // row within pass
            int col0 = lane & 7;             // float4 column start
#pragma unroll
            for (int pass = 0; pass < 8; ++pass) {
                int r = fw * 32 + pass * 4 + sub;
                const float4* rp = fgb + (size_t)r * (H_ / 4) + col0;
                float4 a0 = rp[0],  a1 = rp[8],  a2 = rp[16], a3 = rp[24];
                float4 a4 = rp[32], a5 = rp[40], a6 = rp[48], a7 = rp[56];
                float s =
                  (((a0.x + a0.y) + (a0.z + a0.w)) + ((a1.x + a1.y) + (a1.z + a1.w))) +
                  (((a2.x + a2.y) + (a2.z + a2.w)) + ((a3.x + a3.y) + (a3.z + a3.w))) +
                  (((a4.x + a4.y) + (a4.z + a4.w)) + ((a5.x + a5.y) + (a5.z + a5.w))) +
                  (((a6.x + a6.y) + (a6.z + a6.w)) + ((a7.x + a7.y) + (a7.z + a7.w)));
                s += __shfl_xor_sync(0xffffffffu, s, 1);
                s += __shfl_xor_sync(0xffffffffu, s, 2);
                s += __shfl_xor_sync(0xffffffffu, s, 4);
                if (col0 == 0) fgsum_s[r] = s;
            }
        } else {
            // ================= scan warm-up (warps 0,1) =================
            const float* base = seq + (size_t)b * T_ * F_ + tid;
            if (chunk != 0) {
                int ts = t0 - WARM;
                xl = __ldg(base + (size_t)(ts - 1) * F_);
#pragma unroll 8
                for (int t = ts; t < t0; ++t) {
                    float xt = __ldg(base + (size_t)t * F_);
                    m = 0.5f * (m + xt);
                    float d = xt - m;
                    v = 0.5f * (v + d * d);
                    c = 0.5f * (c + d * (xl - m));
                    xl = xt;
                }
            } else {
                xl = __ldg(base);            // x[0]; state stays (0, EPS, 0)
            }
        }

        __syncthreads();                     // fgsum_s ready; scan state warm

        if (warp < 2) {
            // ================= scan main (warps 0,1) =================
            const float* base = seq + (size_t)b * T_ * F_ + tid;
            int tb;
            if (chunk == 0) { acc = fgsum_s[0]; tb = 1; }   // t=0 pad: irr==1
            else              tb = t0;
#pragma unroll 8
            for (int t = tb; t < t0 + CHUNK; ++t) {
                float xt = __ldg(base + (size_t)t * F_);
                m = 0.5f * (m + xt);
                float d = xt - m;
                v = 0.5f * (v + d * d);
                c = 0.5f * (c + d * (xl - m));
                xl = xt;
                float ac = c * rsqrtf(v * v + EPSV);
                acc += (1.0f - fabsf(ac)) * fgsum_s[t - t0];
            }
#pragma unroll
            for (int o = 16; o > 0; o >>= 1) acc += __shfl_xor_sync(0xffffffffu, acc, o);
            if (lane == 0) sh[warp] = acc;
        }
        __syncthreads();
        if (tid == 0) {
            // ALPHA / (B*T*H*F) = 0.5 / 2^32
            g_part[blockIdx.x] = (sh[0] + sh[1]) * (0.5f / 4294967296.0f);
        }
    } else {
        // ================= MSE role =================
        int bid = blockIdx.x - NS;
        const int n4 = (B_ * T_) / 4;
        float acc = 0.f;
        for (int i = bid * 128 + tid; i < n4; i += NM * 128) {
            float4 a = inp[i], b = tgt[i];
            float dx = a.x - b.x, dy = a.y - b.y, dz = a.z - b.z, dw = a.w - b.w;
            acc += dx * dx + dy * dy + dz * dz + dw * dw;
        }
#pragma unroll
        for (int o = 16; o > 0; o >>= 1) acc += __shfl_xor_sync(0xffffffffu, acc, o);
        if (lane == 0) sh[warp] = acc;
        __syncthreads();
        if (tid == 0)
            g_part[blockIdx.x] = (sh[0] + sh[1] + sh[2] + sh[3]) * (1.0f / ((float)B_ * T_));
    }

    // ---- last-block finalize (threadfence reduction, graph-replay safe) ----
    if (tid == 0) {
        __threadfence();
        unsigned int t = atomicAdd(&g_cnt, 1u);
        is_last = (t == NB - 1);
    }
    __syncthreads();
    if (is_last) {
        double s = 0.0;
        for (int i = tid; i < NB; i += 128) s += (double)g_part[i];
#pragma unroll
        for (int o = 16; o > 0; o >>= 1) s += __shfl_xor_sync(0xffffffffu, s, o);
        __shared__ double sd[4];
        if (lane == 0) sd[warp] = s;
        __syncthreads();
        if (tid == 0) {
            out[0] = (float)(sd[0] + sd[1] + sd[2] + sd[3]);
            g_cnt = 0;                       // reset for next graph replay
        }
    }
}

// ---------------------------------------------------------------------------
extern "C" void kernel_launch(void* const* d_in, const int* in_sizes, int n_in,
                              void* d_out, int out_size) {
    const float* input  = (const float*)d_in[0];
    const float* target = (const float*)d_in[1];
    const float* seq    = (const float*)d_in[2];
    const float* fg     = (const float*)d_in[3];

    k_main<<<NB, 128>>>(seq, (const float4*)fg,
                        (const float4*)input, (const float4*)target,
                        (float*)d_out);
}